// round 12
// baseline (speedup 1.0000x reference)
#include <cuda_runtime.h>

// Fused HybridSamplerConv, round 11: R10 kernel, corrected persistent grid.
// R10 discovery: the rolled-loop form compiles to regs=42, which permits
// 6 blocks/SM — but only 4/SM were launched (608 blocks), capping occupancy
// at 46.5%. This round: 152 x 6 = 912 blocks -> 48 warps/SM,
// 48 x 6 x 128B = 36.9 KB in flight/SM (1.5x the Little's-law requirement),
// with the per-warp load batch kept at the proven 6 LDG.128.

__device__ __forceinline__ float tanh_fast(float x) {
    float y;
    asm("tanh.approx.f32 %0, %1;" : "=f"(y) : "f"(x));
    return y;
}

__global__ void __launch_bounds__(256)
hybrid_sampler_kernel(const float4* __restrict__ inp,    // [B/2]
                      const float4* __restrict__ data,   // [B]
                      const float4* __restrict__ conv_w,
                      const float*  __restrict__ conv_b,
                      const float4* __restrict__ w1v,    // 3 x float4
                      const float4* __restrict__ b1v,
                      const float4* __restrict__ w2v,    // 2 x float4
                      const float2* __restrict__ b2v,
                      float4*       __restrict__ out,    // [B/2]
                      int nquads)                        // B/4
{
    // --- uniform parameter loads: once per thread, L1-broadcast ---
    float4 cw   = __ldg(conv_w);
    float  cb   = __ldg(conv_b);
    float4 w1r0 = __ldg(w1v + 0);
    float4 w1r1 = __ldg(w1v + 1);
    float4 w1r2 = __ldg(w1v + 2);
    float4 b1   = __ldg(b1v);
    float4 w2a  = __ldg(w2v + 0);   // (w2[0][0], w2[0][1], w2[1][0], w2[1][1])
    float4 w2b  = __ldg(w2v + 1);   // (w2[2][0], w2[2][1], w2[3][0], w2[3][1])
    float2 b2   = __ldg(b2v);

    // Fold output layer to logit-difference weights (w2/b2 die here).
    float g0 = w2a.y - w2a.x;
    float g1 = w2a.w - w2a.z;
    float g2 = w2b.y - w2b.x;
    float g3 = w2b.w - w2b.z;
    float gb = b2.y  - b2.x;

    int stride = gridDim.x * blockDim.x;

#pragma unroll 2
    for (int i = blockIdx.x * blockDim.x + threadIdx.x; i < nquads; i += stride) {
        // 6x 128-bit streaming loads, front-batched (MLP_p1 = 6)
        float4 inA = inp[2 * i + 0];
        float4 inB = inp[2 * i + 1];
        float4 d0  = data[4 * i + 0];
        float4 d1  = data[4 * i + 1];
        float4 d2  = data[4 * i + 2];
        float4 d3  = data[4 * i + 3];

        float4 resA, resB;

#pragma unroll
        for (int s = 0; s < 4; ++s) {
            float in0, in1;
            float4 d;
            if      (s == 0) { in0 = inA.x; in1 = inA.y; d = d0; }
            else if (s == 1) { in0 = inA.z; in1 = inA.w; d = d1; }
            else if (s == 2) { in0 = inB.x; in1 = inB.y; d = d2; }
            else             { in0 = inB.z; in1 = inB.w; d = d3; }

            // conv 2x2 -> sigmoid via tanh identity (THRESHOLD = 0)
            float logit = fmaf(d.x, cw.x, fmaf(d.y, cw.y,
                          fmaf(d.z, cw.z, fmaf(d.w, cw.w, cb))));
            float conv = fmaf(tanh_fast(0.5f * logit), 0.5f, 0.5f);

            // h = tanh([in0, in1, conv] @ w1 + b1)
            float h0 = tanh_fast(fmaf(in0, w1r0.x, fmaf(in1, w1r1.x, fmaf(conv, w1r2.x, b1.x))));
            float h1 = tanh_fast(fmaf(in0, w1r0.y, fmaf(in1, w1r1.y, fmaf(conv, w1r2.y, b1.y))));
            float h2 = tanh_fast(fmaf(in0, w1r0.z, fmaf(in1, w1r1.z, fmaf(conv, w1r2.z, b1.z))));
            float h3 = tanh_fast(fmaf(in0, w1r0.w, fmaf(in1, w1r1.w, fmaf(conv, w1r2.w, b1.w))));

            // dz = z1 - z0, then exact softmax-of-2 from the difference
            float dz = fmaf(h0, g0, fmaf(h1, g1, fmaf(h2, g2, fmaf(h3, g3, gb))));
            float e = __expf(dz);
            float r = 1.0f / (1.0f + e);
            float o0 = r, o1 = e * r;

            if      (s == 0) { resA.x = o0; resA.y = o1; }
            else if (s == 1) { resA.z = o0; resA.w = o1; }
            else if (s == 2) { resB.x = o0; resB.y = o1; }
            else             { resB.z = o0; resB.w = o1; }
        }

        out[2 * i + 0] = resA;
        out[2 * i + 1] = resB;
    }
}

extern "C" void kernel_launch(void* const* d_in, const int* in_sizes, int n_in,
                              void* d_out, int out_size)
{
    const float* inp    = (const float*)d_in[0]; // [B,2]
    const float* data   = (const float*)d_in[1]; // [B,2,2]
    const float* conv_w = (const float*)d_in[2];
    const float* conv_b = (const float*)d_in[3];
    const float* w1     = (const float*)d_in[4];
    const float* b1     = (const float*)d_in[5];
    const float* w2     = (const float*)d_in[6];
    const float* b2     = (const float*)d_in[7];
    float* out          = (float*)d_out;

    int B = in_sizes[0] / 2;   // samples
    int nquads = B / 4;        // 4 samples per iteration per thread

    // Persistent grid sized to the 42-reg occupancy tier: 6 blocks/SM.
    int threads = 256;
    int blocks = 152 * 6;      // 912

    hybrid_sampler_kernel<<<blocks, threads>>>(
        (const float4*)inp, (const float4*)data,
        (const float4*)conv_w, conv_b,
        (const float4*)w1, (const float4*)b1,
        (const float4*)w2, (const float2*)b2,
        (float4*)out, nquads);
}

// round 13
// speedup vs baseline: 1.1604x; 1.1604x over previous
#include <cuda_runtime.h>

// Fused HybridSamplerConv, round 12: proven R7 structure (one node, 4096
// blocks, 4 samples/thread, 6 front-batched LDG.128 — best measured config)
// + streaming cache hints: __ldcs on read-once inputs/data, __stcs on
// write-once out, so 134MB of no-reuse traffic stops churning L2.

__device__ __forceinline__ float tanh_fast(float x) {
    float y;
    asm("tanh.approx.f32 %0, %1;" : "=f"(y) : "f"(x));
    return y;
}

__global__ void __launch_bounds__(256)
hybrid_sampler_kernel(const float4* __restrict__ inp,    // [B/2]: 2 samples per float4
                      const float4* __restrict__ data,   // [B]:   1 sample per float4
                      const float4* __restrict__ conv_w,
                      const float*  __restrict__ conv_b,
                      const float4* __restrict__ w1v,    // 3 x float4
                      const float4* __restrict__ b1v,
                      const float4* __restrict__ w2v,    // 2 x float4
                      const float2* __restrict__ b2v,
                      float4*       __restrict__ out,    // [B/2]
                      int nquads)                        // B/4
{
    int i = blockIdx.x * blockDim.x + threadIdx.x;
    if (i >= nquads) return;

    // --- streaming loads: 6x 128-bit, front-batched, evict-first ---
    float4 inA = __ldcs(inp + 2 * i + 0);
    float4 inB = __ldcs(inp + 2 * i + 1);
    float4 d0  = __ldcs(data + 4 * i + 0);
    float4 d1  = __ldcs(data + 4 * i + 1);
    float4 d2  = __ldcs(data + 4 * i + 2);
    float4 d3  = __ldcs(data + 4 * i + 3);

    // --- uniform parameter loads (reused -> normal cached path) ---
    float4 cw   = __ldg(conv_w);
    float  cb   = __ldg(conv_b);
    float4 w1r0 = __ldg(w1v + 0);
    float4 w1r1 = __ldg(w1v + 1);
    float4 w1r2 = __ldg(w1v + 2);
    float4 b1   = __ldg(b1v);
    float4 w2a  = __ldg(w2v + 0);   // (w2[0][0], w2[0][1], w2[1][0], w2[1][1])
    float4 w2b  = __ldg(w2v + 1);   // (w2[2][0], w2[2][1], w2[3][0], w2[3][1])
    float2 b2   = __ldg(b2v);

    // Fold output layer to logit-difference weights (w2/b2 die here).
    float g0 = w2a.y - w2a.x;
    float g1 = w2a.w - w2a.z;
    float g2 = w2b.y - w2b.x;
    float g3 = w2b.w - w2b.z;
    float gb = b2.y  - b2.x;

    float4 resA, resB;

#pragma unroll
    for (int s = 0; s < 4; ++s) {
        float in0, in1;
        float4 d;
        if      (s == 0) { in0 = inA.x; in1 = inA.y; d = d0; }
        else if (s == 1) { in0 = inA.z; in1 = inA.w; d = d1; }
        else if (s == 2) { in0 = inB.x; in1 = inB.y; d = d2; }
        else             { in0 = inB.z; in1 = inB.w; d = d3; }

        // conv 2x2 -> sigmoid via tanh identity (THRESHOLD = 0)
        float logit = fmaf(d.x, cw.x, fmaf(d.y, cw.y,
                      fmaf(d.z, cw.z, fmaf(d.w, cw.w, cb))));
        float conv = fmaf(tanh_fast(0.5f * logit), 0.5f, 0.5f);

        // h = tanh([in0, in1, conv] @ w1 + b1)
        float h0 = tanh_fast(fmaf(in0, w1r0.x, fmaf(in1, w1r1.x, fmaf(conv, w1r2.x, b1.x))));
        float h1 = tanh_fast(fmaf(in0, w1r0.y, fmaf(in1, w1r1.y, fmaf(conv, w1r2.y, b1.y))));
        float h2 = tanh_fast(fmaf(in0, w1r0.z, fmaf(in1, w1r1.z, fmaf(conv, w1r2.z, b1.z))));
        float h3 = tanh_fast(fmaf(in0, w1r0.w, fmaf(in1, w1r1.w, fmaf(conv, w1r2.w, b1.w))));

        // dz = z1 - z0, then exact softmax-of-2 from the difference
        float dz = fmaf(h0, g0, fmaf(h1, g1, fmaf(h2, g2, fmaf(h3, g3, gb))));
        float e = __expf(dz);
        float r = 1.0f / (1.0f + e);
        float o0 = r, o1 = e * r;

        if      (s == 0) { resA.x = o0; resA.y = o1; }
        else if (s == 1) { resA.z = o0; resA.w = o1; }
        else if (s == 2) { resB.x = o0; resB.y = o1; }
        else             { resB.z = o0; resB.w = o1; }
    }

    // write-once streaming stores
    __stcs(out + 2 * i + 0, resA);
    __stcs(out + 2 * i + 1, resB);
}

extern "C" void kernel_launch(void* const* d_in, const int* in_sizes, int n_in,
                              void* d_out, int out_size)
{
    const float* inp    = (const float*)d_in[0]; // [B,2]
    const float* data   = (const float*)d_in[1]; // [B,2,2]
    const float* conv_w = (const float*)d_in[2];
    const float* conv_b = (const float*)d_in[3];
    const float* w1     = (const float*)d_in[4];
    const float* b1     = (const float*)d_in[5];
    const float* w2     = (const float*)d_in[6];
    const float* b2     = (const float*)d_in[7];
    float* out          = (float*)d_out;

    int B = in_sizes[0] / 2;   // samples
    int nquads = B / 4;        // 4 samples per thread

    int threads = 256;
    int blocks = (nquads + threads - 1) / threads;   // 4096

    hybrid_sampler_kernel<<<blocks, threads>>>(
        (const float4*)inp, (const float4*)data,
        (const float4*)conv_w, conv_b,
        (const float4*)w1, (const float4*)b1,
        (const float4*)w2, (const float2*)b2,
        (float4*)out, nquads);
}